// round 17
// baseline (speedup 1.0000x reference)
#include <cuda_runtime.h>
#include <math.h>

#define NN 4096
#define EE 131072
#define CC 64
#define TT 32
#define SSC 5
#define LL 2
#define HRR 64
#define SHH 16
#define EPSF 1e-9f
#define TE 256            // edges per edge-kernel block
#define YCH 128           // Y staging chunk (edges) in node kernel

typedef unsigned long long u64;

__device__ __forceinline__ u64 pk2(float a, float b) {
    u64 r; asm("mov.b64 %0,{%1,%2};" : "=l"(r) : "f"(a), "f"(b)); return r;
}
__device__ __forceinline__ u64 dup2(float a) { return pk2(a, a); }
__device__ __forceinline__ void upk2(u64 v, float& a, float& b) {
    asm("mov.b64 {%0,%1},%2;" : "=f"(a), "=f"(b) : "l"(v));
}
__device__ __forceinline__ void fma2(u64& d, u64 a, u64 b) {
    asm("fma.rn.f32x2 %0,%1,%2,%0;" : "+l"(d) : "l"(a), "l"(b));
}
__device__ __forceinline__ u64 add2(u64 a, u64 b) {
    u64 r; asm("add.rn.f32x2 %0,%1,%2;" : "=l"(r) : "l"(a), "l"(b)); return r;
}
__device__ __forceinline__ u64 mul2(u64 a, u64 b) {
    u64 r; asm("mul.rn.f32x2 %0,%1,%2;" : "=l"(r) : "l"(a), "l"(b)); return r;
}

// ---------------- device scratch (static, zero-initialized at load) ----------------
__device__ int    g_cnt[NN];
__device__ int    g_cur[NN];
__device__ int    g_off[NN + 1];
__device__ int    g_ss[EE];            // sorted send
__device__ int    g_sr[EE];            // sorted recv
__device__ float  g_hs[NN * CC];       // layer-0 node scalars
__device__ u64    g_nf2[NN * 8 * CC];  // node feats after layer 0: [n][xpair][c] f32x2
__device__ float4 g_Y[EE * 4];         // Y per sorted edge
__device__ float  g_R[EE * CC];        // layer0: R*hs/AVG ; layer1: R/AVG
__device__ float  g_pos1[NN * 3];

// ---------------- fused: histogram (int4-vectorized) + node embedding ----------------
__global__ void k_hist_prep(const int* __restrict__ ei,
                            const int* __restrict__ attrs,
                            const float* __restrict__ timeE,
                            const float* __restrict__ eW,
                            const float* __restrict__ eB) {
    int b = blockIdx.x;
    int t = threadIdx.x;
    if (b < 128) {
        int e4 = b * 256 + t;
        int4 r4 = ((const int4*)(ei + EE))[e4];
        atomicAdd(&g_cnt[r4.x], 1);
        atomicAdd(&g_cnt[r4.y], 1);
        atomicAdd(&g_cnt[r4.z], 1);
        atomicAdd(&g_cnt[r4.w], 1);
    } else {
        int n = (b - 128) * 4 + (t >> 6);
        int c = t & 63;
        int a = attrs[n] - 1;
        float v = eB[c] + eW[a * CC + c];
        const float* tb = timeE + n * TT;
#pragma unroll
        for (int k = 0; k < TT; k++) v += tb[k] * eW[(SSC + k) * CC + c];
        g_hs[n * CC + c] = v;
    }
}

// ---------------- scan + counter re-zero ----------------
__global__ void k_scan() {
    __shared__ int sh[1024];
    int t = threadIdx.x;
    int4 v = ((const int4*)g_cnt)[t];
    int s = v.x + v.y + v.z + v.w;
    sh[t] = s;
    __syncthreads();
    for (int o = 1; o < 1024; o <<= 1) {
        int add = (t >= o) ? sh[t - o] : 0;
        __syncthreads();
        sh[t] += add;
        __syncthreads();
    }
    int excl = (t == 0) ? 0 : sh[t - 1];
    g_off[4 * t + 0] = excl;
    g_off[4 * t + 1] = excl + v.x;
    g_off[4 * t + 2] = excl + v.x + v.y;
    g_off[4 * t + 3] = excl + v.x + v.y + v.z;
    if (t == 1023) g_off[NN] = sh[1023];
    ((int4*)g_cnt)[t] = make_int4(0, 0, 0, 0);
    ((int4*)g_cur)[t] = make_int4(0, 0, 0, 0);
}

// ---------------- edge kernel: single-chunk H tile, one barrier (R14/R16 optimum) ----------------
#define ESM_H    (64 * 260 * 4)                      // 66560
#define ESM_W    (HRR * 40 * 8)                      // 20480
#define ESM_MISC (3 * HRR * 4 + TE * 4 + 2 * TE * 4)
#define ESM_TOT  (ESM_H + ESM_W + ESM_MISC)

template <int LAYER>
__global__ void __launch_bounds__(512, 2) k_edge(const int* __restrict__ ei,
                                                 const float* __restrict__ pos0,
                                                 const float* __restrict__ W1,
                                                 const float* __restrict__ B1,
                                                 const float* __restrict__ W2full) {
    extern __shared__ char esm[];
    float (*sH)[260] = (float(*)[260])esm;
    u64*   sW2v = (u64*)(esm + ESM_H);
    float* sW1a = (float*)(esm + ESM_H + ESM_W);
    float* sW1b = sW1a + HRR;
    float* sBB  = sW1b + HRR;
    int*   sP   = (int*)(sBB + HRR);
    float* sLen = (float*)(sP + TE);   // [0..TE): len0, [TE..2TE): len

    int t = threadIdx.x;
    const float* w2 = W2full + LAYER * HRR * CC;
    for (int idx = t; idx < HRR * 32; idx += 512) {
        int j = idx >> 5, q = idx & 31;
        int sub = q >> 3, k = q & 7;
        sW2v[j * 40 + sub * 10 + k] = ((const u64*)(w2 + j * CC))[q];
    }
    if (t < HRR) {
        sW1a[t] = W1[LAYER * 2 * HRR + t];
        sW1b[t] = W1[LAYER * 2 * HRR + HRR + t];
        sBB[t]  = B1[LAYER * HRR + t];
    }

    if (t < TE) {
        int e = blockIdx.x * TE + t;
        int s, r, p;
        if (LAYER == 0) {
            s = ei[e]; r = ei[EE + e];
            p = g_off[r] + atomicAdd(&g_cur[r], 1);
            g_ss[p] = s; g_sr[p] = r;
        } else {
            s = g_ss[e]; r = g_sr[e];
            p = e;
        }
        sP[t] = p;

        float ax = pos0[s * 3], ay = pos0[s * 3 + 1], az = pos0[s * 3 + 2];
        float bx = pos0[r * 3], by = pos0[r * 3 + 1], bz = pos0[r * 3 + 2];
        float dx = bx - ax, dy = by - ay, dz = bz - az;
        float len0 = sqrtf(dx * dx + dy * dy + dz * dz);
        float vx, vy, vz, len;
        if (LAYER == 0) {
            vx = dx; vy = dy; vz = dz; len = len0;
        } else {
            vx = g_pos1[r * 3]     - g_pos1[s * 3];
            vy = g_pos1[r * 3 + 1] - g_pos1[s * 3 + 1];
            vz = g_pos1[r * 3 + 2] - g_pos1[s * 3 + 2];
            len = sqrtf(vx * vx + vy * vy + vz * vz);
        }
        sLen[t]      = len0;
        sLen[TE + t] = len;
        float inv = 1.0f / (len + EPSF);
        float x = vx * inv, y = vy * inv, z = vz * inv;
        float xx = x * x, yy = y * y, zz = z * z;
        float4* yp = (float4*)&g_Y[p * 4];
        yp[0] = make_float4(1.0f,
                            1.7320508075688772f * x,
                            1.7320508075688772f * y,
                            1.7320508075688772f * z);
        yp[1] = make_float4(3.872983346207417f * x * y,
                            3.872983346207417f * y * z,
                            1.118033988749895f * (3.0f * zz - 1.0f),
                            3.872983346207417f * x * z);
        yp[2] = make_float4(1.9364916731037085f * (xx - yy),
                            2.091650066335189f * y * (3.0f * xx - yy),
                            10.246950765959598f * x * y * z,
                            1.6201851746019651f * y * (5.0f * zz - 1.0f));
        yp[3] = make_float4(1.3228756555322954f * z * (5.0f * zz - 3.0f),
                            1.6201851746019651f * x * (5.0f * zz - 1.0f),
                            5.123475382979799f * z * (xx - yy),
                            2.091650066335189f * x * (xx - 3.0f * yy));
    }
    __syncthreads();

    // silu for all 64 j: 512 threads, each does 32 j for one edge
    {
        const float invAvg = 1.0f / 32.0f;
        int se = t & 255;
        int sg = t >> 8;          // 0..1, j-range sg*32..sg*32+31
        float l0 = sLen[se], l1 = sLen[TE + se];
#pragma unroll
        for (int jj = 0; jj < 32; jj++) {
            int j = sg * 32 + jj;
            float a = fmaf(l0, sW1a[j], fmaf(l1, sW1b[j], sBB[j]));
            sH[j][se] = __fdividef(a, 1.0f + __expf(-a)) * invAvg;
        }
    }
    __syncthreads();

    int sub = t & 3;
    int eg  = t >> 2;
    u64 acc[2][8];
#pragma unroll
    for (int ed = 0; ed < 2; ed++)
#pragma unroll
        for (int k = 0; k < 8; k++) acc[ed][k] = 0ull;

#pragma unroll 8
    for (int j = 0; j < HRR; j++) {
        float2 h2 = *(const float2*)&sH[j][eg * 2];
        u64 hd0 = dup2(h2.x), hd1 = dup2(h2.y);
        const ulonglong2* wr = (const ulonglong2*)&sW2v[j * 40 + sub * 10];
        ulonglong2 wA = wr[0], wB = wr[1], wC = wr[2], wD = wr[3];
        fma2(acc[0][0], hd0, wA.x); fma2(acc[0][1], hd0, wA.y);
        fma2(acc[0][2], hd0, wB.x); fma2(acc[0][3], hd0, wB.y);
        fma2(acc[0][4], hd0, wC.x); fma2(acc[0][5], hd0, wC.y);
        fma2(acc[0][6], hd0, wD.x); fma2(acc[0][7], hd0, wD.y);
        fma2(acc[1][0], hd1, wA.x); fma2(acc[1][1], hd1, wA.y);
        fma2(acc[1][2], hd1, wB.x); fma2(acc[1][3], hd1, wB.y);
        fma2(acc[1][4], hd1, wC.x); fma2(acc[1][5], hd1, wC.y);
        fma2(acc[1][6], hd1, wD.x); fma2(acc[1][7], hd1, wD.y);
    }

#pragma unroll
    for (int ed = 0; ed < 2; ed++) {
        int p = sP[eg * 2 + ed];
        u64 o[8];
        if (LAYER == 0) {
            int s = g_ss[p];                 // L1-hot
            const ulonglong2* hp = (const ulonglong2*)&g_hs[s * CC + sub * 16];
            ulonglong2 hA = hp[0], hB = hp[1], hC = hp[2], hD = hp[3];
            o[0] = mul2(acc[ed][0], hA.x); o[1] = mul2(acc[ed][1], hA.y);
            o[2] = mul2(acc[ed][2], hB.x); o[3] = mul2(acc[ed][3], hB.y);
            o[4] = mul2(acc[ed][4], hC.x); o[5] = mul2(acc[ed][5], hC.y);
            o[6] = mul2(acc[ed][6], hD.x); o[7] = mul2(acc[ed][7], hD.y);
        } else {
#pragma unroll
            for (int k = 0; k < 8; k++) o[k] = acc[ed][k];
        }
        ulonglong2* dst = (ulonglong2*)&g_R[p * CC + sub * 16];
        ulonglong2 v0; v0.x = o[0]; v0.y = o[1];
        ulonglong2 v1; v1.x = o[2]; v1.y = o[3];
        ulonglong2 v2; v2.x = o[4]; v2.y = o[5];
        ulonglong2 v3; v3.x = o[6]; v3.y = o[7];
        dst[0] = v0; dst[1] = v1; dst[2] = v2; dst[3] = v3;
    }
}

// ---------------- per-node: aggregate + mix + gate + prod + pos ----------------
// R16 structure; layer-0 'extra' folded into a2[0] (bit-exact), final
// reduction parallelized (192 threads, shfl tree) to shrink the block tail.
template <int LAYER>
__global__ void __launch_bounds__(256, 4) k_node(const float* __restrict__ pos_in,
                                                 const float* __restrict__ pos0,
                                                 const float* __restrict__ Wmix,
                                                 const float* __restrict__ Wprod,
                                                 const float* __restrict__ Wvec,
                                                 float* __restrict__ pos_out) {
    constexpr bool LAST = (LAYER == LL - 1);
    int t = threadIdx.x;
    int g = t >> 6;
    int d = t & 63;
    int base = blockIdx.x * 4;
    int n = base + g;

    __shared__ __align__(16) float sY[YCH * 16];
    __shared__ int sSS[YCH];
    __shared__ __align__(16) float sS[4][64][16];
    __shared__ float sG[4][64];
    __shared__ float sV[4][3][64];

    u64 a2[8];
#pragma unroll
    for (int q = 0; q < 8; q++) a2[q] = 0ull;
    float extra = 0.f;

    int e0 = g_off[n], e1 = g_off[n + 1];
    int E0 = g_off[base], E1 = g_off[base + 4];

    for (int ch = E0; ch < E1; ch += YCH) {
        int cend = (ch + YCH < E1) ? (ch + YCH) : E1;
        int cnt = cend - ch;
        __syncthreads();
        {
            const float4* src = (const float4*)&g_Y[ch * 4];
            float4* dst = (float4*)sY;
            for (int i = t; i < cnt * 4; i += 256) dst[i] = src[i];
            if (LAYER == 1) {
                for (int i = t; i < cnt; i += 256) sSS[i] = g_ss[ch + i];
            }
        }
        __syncthreads();

        int lo = (e0 > ch) ? e0 : ch;
        int hi = (e1 < cend) ? e1 : cend;
        if (LAYER == 0) {
#pragma unroll 4
            for (int e = lo; e < hi; ++e) {
                const ulonglong2* up = (const ulonglong2*)&sY[(e - ch) * 16];
                ulonglong2 U0 = up[0], U1 = up[1], U2 = up[2], U3 = up[3];
                float Rc = g_R[e * CC + d];
                u64 wd = dup2(Rc);
                fma2(a2[0], wd, U0.x); fma2(a2[1], wd, U0.y);
                fma2(a2[2], wd, U1.x); fma2(a2[3], wd, U1.y);
                fma2(a2[4], wd, U2.x); fma2(a2[5], wd, U2.y);
                fma2(a2[6], wd, U3.x); fma2(a2[7], wd, U3.y);
            }
        } else {
#pragma unroll 2
            for (int e = lo; e < hi; ++e) {
                const ulonglong2* up = (const ulonglong2*)&sY[(e - ch) * 16];
                ulonglong2 U0 = up[0], U1 = up[1], U2 = up[2], U3 = up[3];
                int s = sSS[e - ch];
                float R = g_R[e * CC + d];
                const u64* hb = &g_nf2[s * 8 * CC + d];
                u64 h0p = __ldg(&hb[0 * CC]);
                u64 h1p = __ldg(&hb[1 * CC]);
                u64 h2p = __ldg(&hb[2 * CC]);
                u64 h3p = __ldg(&hb[3 * CC]);
                u64 h4p = __ldg(&hb[4 * CC]);
                u64 h5p = __ldg(&hb[5 * CC]);
                u64 h6p = __ldg(&hb[6 * CC]);
                u64 h7p = __ldg(&hb[7 * CC]);
                u64 tp2 = 0ull;
                fma2(tp2, h0p, U0.x); fma2(tp2, h1p, U0.y);
                fma2(tp2, h2p, U1.x); fma2(tp2, h3p, U1.y);
                fma2(tp2, h4p, U2.x); fma2(tp2, h5p, U2.y);
                fma2(tp2, h6p, U3.x); fma2(tp2, h7p, U3.y);
                float tl, th; upk2(tp2, tl, th);
                extra = fmaf(R, tl + th, extra);
                float h0, h1u; upk2(h0p, h0, h1u);
                u64 wd = dup2(R * h0);
                fma2(a2[0], wd, U0.x); fma2(a2[1], wd, U0.y);
                fma2(a2[2], wd, U1.x); fma2(a2[3], wd, U1.y);
                fma2(a2[4], wd, U2.x); fma2(a2[5], wd, U2.y);
                fma2(a2[6], wd, U3.x); fma2(a2[7], wd, U3.y);
            }
        }
    }

    float av[16];
#pragma unroll
    for (int q = 0; q < 8; q++) upk2(a2[q], av[2 * q], av[2 * q + 1]);
    if (LAYER == 0) av[0] += av[0];   // tp term == m term (Y0=1, same sum order)
    else            av[0] += extra;
    {
        float4* st = (float4*)&sS[g][d][0];
        st[0] = make_float4(av[0], av[1], av[2], av[3]);
        st[1] = make_float4(av[4], av[5], av[6], av[7]);
        st[2] = make_float4(av[8], av[9], av[10], av[11]);
        st[3] = make_float4(av[12], av[13], av[14], av[15]);
    }
    __syncthreads();

    // ---- mix ----
    u64 m2[8];
#pragma unroll
    for (int q = 0; q < 8; q++) m2[q] = 0ull;
    const float* Wm = Wmix + LAYER * 4 * CC * CC + d;
#pragma unroll 4
    for (int cc = 0; cc < CC; cc++) {
        float w0 = Wm[(0 * CC + cc) * CC];
        float w1 = Wm[(1 * CC + cc) * CC];
        float w2 = Wm[(2 * CC + cc) * CC];
        float w3 = Wm[(3 * CC + cc) * CC];
        u64 W01 = pk2(w0, w1), W11 = dup2(w1), W22 = dup2(w2);
        u64 W23 = pk2(w2, w3), W33 = dup2(w3);
        const ulonglong2* ap = (const ulonglong2*)&sS[g][cc][0];
        ulonglong2 A = ap[0], B = ap[1], Cq = ap[2], D = ap[3];
        fma2(m2[0], A.x, W01);  fma2(m2[1], A.y, W11);
        fma2(m2[2], B.x, W22);  fma2(m2[3], B.y, W22);
        fma2(m2[4], Cq.x, W23); fma2(m2[5], Cq.y, W33);
        fma2(m2[6], D.x, W33);  fma2(m2[7], D.y, W33);
    }
    __syncthreads();

    // ---- stage mixed + gate ----
    {
        ulonglong2* st2 = (ulonglong2*)&sS[g][d][0];
        ulonglong2 v0; v0.x = m2[0]; v0.y = m2[1]; st2[0] = v0;
        ulonglong2 v1; v1.x = m2[2]; v1.y = m2[3]; st2[1] = v1;
        ulonglong2 v2; v2.x = m2[4]; v2.y = m2[5]; st2[2] = v2;
        ulonglong2 v3; v3.x = m2[6]; v3.y = m2[7]; st2[3] = v3;
        float s0, s1; upk2(m2[0], s0, s1);
        sG[g][d] = s0 * (1.0f + s0 + s0 * s0);
    }
    __syncthreads();

    // ---- prod (gate folded into weight) ----
    u64 p2[8];
#pragma unroll
    for (int q = 0; q < 8; q++) p2[q] = 0ull;
    const float* Wp = Wprod + LAYER * CC * CC + d;
#pragma unroll 4
    for (int cc = 0; cc < CC; cc++) {
        u64 wg = dup2(Wp[cc * CC] * sG[g][cc]);
        const ulonglong2* ap = (const ulonglong2*)&sS[g][cc][0];
        ulonglong2 A = ap[0], B = ap[1], Cq = ap[2], D = ap[3];
        fma2(p2[0], A.x, wg);  fma2(p2[1], A.y, wg);
        fma2(p2[2], B.x, wg);  fma2(p2[3], B.y, wg);
        fma2(p2[4], Cq.x, wg); fma2(p2[5], Cq.y, wg);
        fma2(p2[6], D.x, wg);  fma2(p2[7], D.y, wg);
    }

    // ---- nf = mixed (reload from smem) + prod; keep as u64 pairs ----
    u64 nfv[8];
    {
        const ulonglong2* ap = (const ulonglong2*)&sS[g][d][0];
        ulonglong2 A = ap[0], B = ap[1], Cq = ap[2], D = ap[3];
        nfv[0] = add2(A.x, p2[0]);  nfv[1] = add2(A.y, p2[1]);
        nfv[2] = add2(B.x, p2[2]);  nfv[3] = add2(B.y, p2[3]);
        nfv[4] = add2(Cq.x, p2[4]); nfv[5] = add2(Cq.y, p2[5]);
        nfv[6] = add2(D.x, p2[6]);  nfv[7] = add2(D.y, p2[7]);
    }

    if (!LAST) {
#pragma unroll
        for (int q = 0; q < 8; q++) g_nf2[(n * 8 + q) * CC + d] = nfv[q];
    }

    float nf0, nf1, nf2f, nf3;
    upk2(nfv[0], nf0, nf1);
    upk2(nfv[1], nf2f, nf3);
    float wv = Wvec[d];
    sV[g][0][d] = nf1 * wv;
    sV[g][1][d] = nf2f * wv;
    sV[g][2][d] = nf3 * wv;
    __syncthreads();

    // parallel tail reduction: 12 sums of 64, 16 lanes each + shfl tree
    if (t < 192) {
        int grp = t >> 4;        // 0..11
        int l16 = t & 15;
        int gg = grp / 3, j = grp % 3;
        float sum = sV[gg][j][l16] + sV[gg][j][l16 + 16]
                  + sV[gg][j][l16 + 32] + sV[gg][j][l16 + 48];
        sum += __shfl_xor_sync(0xffffffffu, sum, 8);
        sum += __shfl_xor_sync(0xffffffffu, sum, 4);
        sum += __shfl_xor_sync(0xffffffffu, sum, 2);
        sum += __shfl_xor_sync(0xffffffffu, sum, 1);
        if (l16 == 0) {
            int nn = base + gg;
            float pp = pos_in[nn * 3 + j] + sum;
            pos_out[nn * 3 + j] = LAST ? (pp - pos0[nn * 3 + j]) : pp;
        }
    }
}

// ---------------- launch ----------------
extern "C" void kernel_launch(void* const* d_in, const int* in_sizes, int n_in,
                              void* d_out, int out_size) {
    const float* positions = (const float*)d_in[0];
    const int*   node_attrs = (const int*)d_in[1];
    const float* time_emb = (const float*)d_in[2];
    const int*   edge_index = (const int*)d_in[3];
    const float* embed_W = (const float*)d_in[4];
    const float* embed_b = (const float*)d_in[5];
    const float* radial_W1 = (const float*)d_in[6];
    const float* radial_b1 = (const float*)d_in[7];
    const float* radial_W2 = (const float*)d_in[8];
    const float* Wmix = (const float*)d_in[9];
    const float* Wprod = (const float*)d_in[10];
    const float* Wvec = (const float*)d_in[11];
    float* out = (float*)d_out;

    float* g_pos1_p = nullptr;
    cudaGetSymbolAddress((void**)&g_pos1_p, g_pos1);

    cudaFuncSetAttribute(k_edge<0>, cudaFuncAttributeMaxDynamicSharedMemorySize, ESM_TOT);
    cudaFuncSetAttribute(k_edge<1>, cudaFuncAttributeMaxDynamicSharedMemorySize, ESM_TOT);

    k_hist_prep<<<128 + 1024, 256>>>(edge_index, node_attrs, time_emb, embed_W, embed_b);
    k_scan<<<1, 1024>>>();
    k_edge<0><<<EE / TE, 512, ESM_TOT>>>(edge_index, positions, radial_W1, radial_b1, radial_W2);
    k_node<0><<<NN / 4, 256>>>(positions, positions, Wmix, Wprod, Wvec + 0 * CC, g_pos1_p);
    k_edge<1><<<EE / TE, 512, ESM_TOT>>>(edge_index, positions, radial_W1, radial_b1, radial_W2);
    k_node<1><<<NN / 4, 256>>>(g_pos1_p, positions, Wmix, Wprod, Wvec + 1 * CC, out);
}